// round 5
// baseline (speedup 1.0000x reference)
#include <cuda_runtime.h>

#define D       64
#define DV      16          // D/4 float4 per row
#define MAX_N   100000
#define EPT     8           // edges per thread in scatter kernel
#define EPB     128         // edges per block (256 threads / 16 lanes * EPT)

// Scratch: Y = X @ W^T, [N, 64] as float4[N*16]. __device__ global (no alloc allowed).
__device__ float4 g_Y[MAX_N * DV];

// f32x2 packed FMA (sm_100+, PTX-only): lanewise (lo,hi) fma on a 64-bit pair.
__device__ __forceinline__ void fma2(unsigned long long& acc,
                                     unsigned long long a,
                                     unsigned long long b) {
    asm("fma.rn.f32x2 %0, %1, %2, %0;" : "+l"(acc) : "l"(a), "l"(b));
}
__device__ __forceinline__ float hadd2(unsigned long long p) {
    float lo, hi;
    asm("mov.b64 {%0, %1}, %2;" : "=f"(lo), "=f"(hi) : "l"(p));
    return lo + hi;
}

// ---------------------------------------------------------------------------
// Kernel 1: Y[n] = X[n] @ W^T ; out[n] = bias
// One node per thread. X row held as 32 f32x2 pairs in regs; W rows read from
// smem as broadcast LDS.128 (all lanes same address -> 1 cyc). FFMA2 doubles
// fma-pipe throughput vs scalar FFMA.
// ---------------------------------------------------------------------------
__global__ __launch_bounds__(256) void xform_init_kernel(
    const float*  __restrict__ X,      // [N, 64]
    const float*  __restrict__ W,      // [64, 64] (row o, k-contiguous)
    const float4* __restrict__ bias,   // [16]
    float4*       __restrict__ out,    // [N*16]
    int N)
{
    __shared__ __align__(16) float Ws[D * D];   // 16KB, natural [o][k]

    for (int i = threadIdx.x; i < D * DV; i += 256)
        ((float4*)Ws)[i] = ((const float4*)W)[i];
    __syncthreads();

    int n = blockIdx.x * 256 + threadIdx.x;
    if (n >= N) return;

    // X row: 64 floats = 16 ulonglong2 = 32 packed f32x2 values
    ulonglong2 xp[16];
    const ulonglong2* Xrow = (const ulonglong2*)(X + (size_t)n * D);
#pragma unroll
    for (int i = 0; i < 16; i++) xp[i] = Xrow[i];

#pragma unroll
    for (int og = 0; og < DV; og++) {           // 16 groups of 4 outputs
        unsigned long long a0 = 0ull, a1 = 0ull, a2 = 0ull, a3 = 0ull;
        const ulonglong2* w0 = (const ulonglong2*)(Ws + (og * 4 + 0) * D);
        const ulonglong2* w1 = (const ulonglong2*)(Ws + (og * 4 + 1) * D);
        const ulonglong2* w2 = (const ulonglong2*)(Ws + (og * 4 + 2) * D);
        const ulonglong2* w3 = (const ulonglong2*)(Ws + (og * 4 + 3) * D);
#pragma unroll
        for (int kq = 0; kq < 16; kq++) {
            ulonglong2 xq = xp[kq];
            ulonglong2 q0 = w0[kq], q1 = w1[kq], q2 = w2[kq], q3 = w3[kq];
            fma2(a0, xq.x, q0.x); fma2(a0, xq.y, q0.y);
            fma2(a1, xq.x, q1.x); fma2(a1, xq.y, q1.y);
            fma2(a2, xq.x, q2.x); fma2(a2, xq.y, q2.y);
            fma2(a3, xq.x, q3.x); fma2(a3, xq.y, q3.y);
        }
        float4 r = make_float4(hadd2(a0), hadd2(a1), hadd2(a2), hadd2(a3));
        size_t o = (size_t)n * DV + og;
        g_Y[o] = r;                 // pure X@W^T (no bias)
        out[o] = __ldg(bias + og);  // bias init (also covers zero-degree nodes)
    }
}

// ---------------------------------------------------------------------------
// Kernel 2: out[row[e]] += vals[e] * Y[col[e]]
// Block stages 128 edges' meta in smem (3 coalesced LDGs), threads read it as
// int4/float4 broadcast LDS. 16 threads per edge (thread q = float4 chunk q),
// EPT=8 edges per thread with front-batched gathers (MLP=8). RED.v4 is
// fire-and-forget.
// ---------------------------------------------------------------------------
__device__ __forceinline__ void red_add_v4(float4* addr, float4 v) {
    asm volatile("red.global.add.v4.f32 [%0], {%1, %2, %3, %4};"
                 :: "l"(addr), "f"(v.x), "f"(v.y), "f"(v.z), "f"(v.w)
                 : "memory");
}

__global__ __launch_bounds__(256) void edge_scatter_kernel(
    const int*   __restrict__ row,
    const int*   __restrict__ col,
    const float* __restrict__ vals,
    float4*      __restrict__ out,
    int E)
{
    __shared__ __align__(16) int   s_col[EPB];
    __shared__ __align__(16) int   s_row[EPB];
    __shared__ __align__(16) float s_val[EPB];

    const int tid  = threadIdx.x;
    const int base = blockIdx.x * EPB;

    if (tid < EPB) {
        int e = base + tid;
        bool ok = e < E;
        s_col[tid] = ok ? __ldg(col  + e) : 0;
        s_row[tid] = ok ? __ldg(row  + e) : 0;
        s_val[tid] = ok ? __ldg(vals + e) : 0.0f;   // val=0 -> RED adds 0, harmless
    }
    __syncthreads();

    const int q = tid & 15;
    const int g = tid >> 4;       // 0..15, handles local edges g*8 .. g*8+7

    // column indices (broadcast LDS.128), then fire all 8 gathers (MLP=8)
    int4 c0 = ((const int4*)s_col)[g * 2];
    int4 c1 = ((const int4*)s_col)[g * 2 + 1];

    float4 y[EPT];
    y[0] = __ldg(&g_Y[(size_t)c0.x * DV + q]);
    y[1] = __ldg(&g_Y[(size_t)c0.y * DV + q]);
    y[2] = __ldg(&g_Y[(size_t)c0.z * DV + q]);
    y[3] = __ldg(&g_Y[(size_t)c0.w * DV + q]);
    y[4] = __ldg(&g_Y[(size_t)c1.x * DV + q]);
    y[5] = __ldg(&g_Y[(size_t)c1.y * DV + q]);
    y[6] = __ldg(&g_Y[(size_t)c1.z * DV + q]);
    y[7] = __ldg(&g_Y[(size_t)c1.w * DV + q]);

    int4   r0 = ((const int4*)s_row)[g * 2];
    int4   r1 = ((const int4*)s_row)[g * 2 + 1];
    float4 v0 = ((const float4*)s_val)[g * 2];
    float4 v1 = ((const float4*)s_val)[g * 2 + 1];

    const int   r[EPT] = {r0.x, r0.y, r0.z, r0.w, r1.x, r1.y, r1.z, r1.w};
    const float v[EPT] = {v0.x, v0.y, v0.z, v0.w, v1.x, v1.y, v1.z, v1.w};

#pragma unroll
    for (int j = 0; j < EPT; j++) {
        float4 m = make_float4(v[j]*y[j].x, v[j]*y[j].y, v[j]*y[j].z, v[j]*y[j].w);
        red_add_v4(out + (size_t)r[j] * DV + q, m);
    }
}

// ---------------------------------------------------------------------------
// Launch: inputs in metadata order: row, col, vals, X, weight, bias
// ---------------------------------------------------------------------------
extern "C" void kernel_launch(void* const* d_in, const int* in_sizes, int n_in,
                              void* d_out, int out_size)
{
    const int*   row  = (const int*)  d_in[0];
    const int*   col  = (const int*)  d_in[1];
    const float* vals = (const float*)d_in[2];
    const float* X    = (const float*)d_in[3];
    const float* W    = (const float*)d_in[4];
    const float* bias = (const float*)d_in[5];
    float*       out  = (float*)d_out;

    int E = in_sizes[0];
    int N = in_sizes[3] / D;   // 100000

    xform_init_kernel<<<(N + 255) / 256, 256>>>(
        X, W, (const float4*)bias, (float4*)out, N);

    int blocks = (E + EPB - 1) / EPB;
    edge_scatter_kernel<<<blocks, 256>>>(
        row, col, vals, (float4*)out, E);
}

// round 7
// speedup vs baseline: 1.1276x; 1.1276x over previous
#include <cuda_runtime.h>

#define D       64
#define DV      16          // D/4 float4 per row
#define MAX_N   100000
#define MAX_E   1700000
#define SCAN_B  1024

// ---------------------------------------------------------------------------
// Device-global scratch (no allocation allowed)
// ---------------------------------------------------------------------------
__device__ int    g_cnt[MAX_N];        // histogram of destination rows
__device__ int    g_off[MAX_N + 1];    // exclusive CSR offsets
__device__ int    g_pos[MAX_N];        // working cursor for binning
__device__ int    g_bsum[256];         // per-block scan totals
__device__ int2   g_edge[MAX_E];       // binned (col, val-bits) pairs
__device__ float4 g_S[MAX_N * DV];     // S = A @ X

// ---------------------------------------------------------------------------
// 0) zero histogram
// ---------------------------------------------------------------------------
__global__ void zero_cnt_kernel(int N) {
    int i = blockIdx.x * SCAN_B + threadIdx.x;
    if (i < N) g_cnt[i] = 0;
}

// ---------------------------------------------------------------------------
// 1) histogram of row[]
// ---------------------------------------------------------------------------
__global__ __launch_bounds__(512) void hist_kernel(const int* __restrict__ row, int E) {
    int e = blockIdx.x * 512 + threadIdx.x;
    if (e < E) atomicAdd(&g_cnt[__ldg(row + e)], 1);
}

// ---------------------------------------------------------------------------
// 2a) per-block exclusive scan of g_cnt -> g_off ; block totals -> g_bsum
// ---------------------------------------------------------------------------
__global__ __launch_bounds__(SCAN_B) void scan_a_kernel(int N) {
    int i = blockIdx.x * SCAN_B + threadIdx.x;
    int v = (i < N) ? g_cnt[i] : 0;

    int lane = threadIdx.x & 31;
    int wid  = threadIdx.x >> 5;

    int s = v;
#pragma unroll
    for (int d = 1; d < 32; d <<= 1) {
        int t = __shfl_up_sync(0xFFFFFFFFu, s, d);
        if (lane >= d) s += t;
    }
    __shared__ int wsum[32];
    if (lane == 31) wsum[wid] = s;
    __syncthreads();
    if (wid == 0) {
        int ws = wsum[lane];
#pragma unroll
        for (int d = 1; d < 32; d <<= 1) {
            int t = __shfl_up_sync(0xFFFFFFFFu, ws, d);
            if (lane >= d) ws += t;
        }
        wsum[lane] = ws;
    }
    __syncthreads();
    int incl = s + (wid == 0 ? 0 : wsum[wid - 1]);
    if (i < N) g_off[i] = incl - v;                    // exclusive
    if (threadIdx.x == SCAN_B - 1) g_bsum[blockIdx.x] = incl;  // block total
}

// ---------------------------------------------------------------------------
// 2b) exclusive scan of block totals (single block, up to 128 blocks)
//     also writes g_off[N] = E
// ---------------------------------------------------------------------------
__global__ __launch_bounds__(128) void scan_b_kernel(int NB, int N) {
    int tid = threadIdx.x;
    int v = (tid < NB) ? g_bsum[tid] : 0;

    int lane = tid & 31;
    int wid  = tid >> 5;
    int s = v;
#pragma unroll
    for (int d = 1; d < 32; d <<= 1) {
        int t = __shfl_up_sync(0xFFFFFFFFu, s, d);
        if (lane >= d) s += t;
    }
    __shared__ int wsum[4];
    if (lane == 31) wsum[wid] = s;
    __syncthreads();
    int wpre = 0;
#pragma unroll
    for (int w = 0; w < 4; w++)
        if (w < wid) wpre += wsum[w];
    int incl = s + wpre;
    g_bsum[tid] = incl - v;                // exclusive block prefix
    if (tid == 127) g_off[N] = incl;       // grand total = E
}

// ---------------------------------------------------------------------------
// 2c) add block prefixes; copy to cursor array
// ---------------------------------------------------------------------------
__global__ __launch_bounds__(SCAN_B) void scan_c_kernel(int N) {
    int i = blockIdx.x * SCAN_B + threadIdx.x;
    if (i < N) {
        int o = g_off[i] + g_bsum[blockIdx.x];
        g_off[i] = o;
        g_pos[i] = o;
    }
}

// ---------------------------------------------------------------------------
// 3) bin edges into CSR order: g_edge[pos] = (col, val)
// ---------------------------------------------------------------------------
__global__ __launch_bounds__(512) void bin_kernel(
    const int* __restrict__ row, const int* __restrict__ col,
    const float* __restrict__ vals, int E)
{
    int e = blockIdx.x * 512 + threadIdx.x;
    if (e < E) {
        int r = __ldg(row + e);
        int p = atomicAdd(&g_pos[r], 1);
        g_edge[p] = make_int2(__ldg(col + e), __float_as_int(__ldg(vals + e)));
    }
}

// ---------------------------------------------------------------------------
// 4) gather: S[n] = sum over in-edges of val * X[col]
//    16 lanes per node, lane q owns float4 chunk q. Unroll-4 for MLP.
// ---------------------------------------------------------------------------
__global__ __launch_bounds__(256) void gather_kernel(
    const float4* __restrict__ X4, int N)
{
    int t = blockIdx.x * 256 + threadIdx.x;
    int n = t >> 4;
    int q = t & 15;
    if (n >= N) return;

    int s = __ldg(&g_off[n]);
    int e = __ldg(&g_off[n + 1]);

    float4 acc = make_float4(0.f, 0.f, 0.f, 0.f);
    int j = s;
    for (; j + 4 <= e; j += 4) {
        int2 p0 = g_edge[j], p1 = g_edge[j + 1], p2 = g_edge[j + 2], p3 = g_edge[j + 3];
        float4 x0 = __ldg(X4 + (size_t)p0.x * DV + q);
        float4 x1 = __ldg(X4 + (size_t)p1.x * DV + q);
        float4 x2 = __ldg(X4 + (size_t)p2.x * DV + q);
        float4 x3 = __ldg(X4 + (size_t)p3.x * DV + q);
        float v0 = __int_as_float(p0.y), v1 = __int_as_float(p1.y);
        float v2 = __int_as_float(p2.y), v3 = __int_as_float(p3.y);
        acc.x += v0 * x0.x; acc.y += v0 * x0.y; acc.z += v0 * x0.z; acc.w += v0 * x0.w;
        acc.x += v1 * x1.x; acc.y += v1 * x1.y; acc.z += v1 * x1.z; acc.w += v1 * x1.w;
        acc.x += v2 * x2.x; acc.y += v2 * x2.y; acc.z += v2 * x2.z; acc.w += v2 * x2.w;
        acc.x += v3 * x3.x; acc.y += v3 * x3.y; acc.z += v3 * x3.z; acc.w += v3 * x3.w;
    }
    for (; j < e; j++) {
        int2 p = g_edge[j];
        float4 x = __ldg(X4 + (size_t)p.x * DV + q);
        float v = __int_as_float(p.y);
        acc.x += v * x.x; acc.y += v * x.y; acc.z += v * x.z; acc.w += v * x.w;
    }
    g_S[(size_t)n * DV + q] = acc;
}

// ---------------------------------------------------------------------------
// 5) GEMM: out = S @ W^T + b
//    Register-tiled: 64x64 block tile, 256 threads, 4x4 micro-tile (R3 proven).
// ---------------------------------------------------------------------------
#define TPAD 68   // row stride in floats (272B, 16B-aligned)

__global__ __launch_bounds__(256) void gemm_bias_kernel(
    const float*  __restrict__ W,      // [64, 64]
    const float4* __restrict__ bias,   // [16]
    float4*       __restrict__ out,    // [N*16]
    int N)
{
    __shared__ float Xs[D * TPAD];   // Xs[k][m]  (S tile, transposed)
    __shared__ float Ws[D * TPAD];   // Ws[k][o]

    const int tid = threadIdx.x;
    const int node0 = blockIdx.x * 64;
    const float* S = (const float*)g_S;

    {
        int r  = tid >> 4;          // 0..15
        int cv = tid & 15;          // float4 column 0..15
#pragma unroll
        for (int p = 0; p < 4; p++) {
            int row = r + p * 16;
            float4 w = *(const float4*)(W + row * D + cv * 4);
            Ws[(cv * 4 + 0) * TPAD + row] = w.x;
            Ws[(cv * 4 + 1) * TPAD + row] = w.y;
            Ws[(cv * 4 + 2) * TPAD + row] = w.z;
            Ws[(cv * 4 + 3) * TPAD + row] = w.w;
            int n = node0 + row;
            float4 x = (n < N) ? *(const float4*)(S + (size_t)n * D + cv * 4)
                               : make_float4(0.f, 0.f, 0.f, 0.f);
            Xs[(cv * 4 + 0) * TPAD + row] = x.x;
            Xs[(cv * 4 + 1) * TPAD + row] = x.y;
            Xs[(cv * 4 + 2) * TPAD + row] = x.z;
            Xs[(cv * 4 + 3) * TPAD + row] = x.w;
        }
    }
    __syncthreads();

    const int tx = tid & 15;
    const int ty = tid >> 4;
    const int m4 = ty * 4;
    const int n4 = tx * 4;

    float acc[4][4];
#pragma unroll
    for (int i = 0; i < 4; i++)
#pragma unroll
        for (int j = 0; j < 4; j++) acc[i][j] = 0.f;

#pragma unroll 8
    for (int k = 0; k < D; k++) {
        float4 xf = *(const float4*)(Xs + k * TPAD + m4);
        float4 wf = *(const float4*)(Ws + k * TPAD + n4);
        const float xv[4] = {xf.x, xf.y, xf.z, xf.w};
        const float wv[4] = {wf.x, wf.y, wf.z, wf.w};
#pragma unroll
        for (int i = 0; i < 4; i++)
#pragma unroll
            for (int j = 0; j < 4; j++)
                acc[i][j] += xv[i] * wv[j];
    }

    float4 b = __ldg(bias + tx);
#pragma unroll
    for (int i = 0; i < 4; i++) {
        int n = node0 + m4 + i;
        if (n < N) {
            out[(size_t)n * DV + tx] =
                make_float4(acc[i][0] + b.x, acc[i][1] + b.y,
                            acc[i][2] + b.z, acc[i][3] + b.w);
        }
    }
}

// ---------------------------------------------------------------------------
// Launch: inputs in metadata order: row, col, vals, X, weight, bias
// ---------------------------------------------------------------------------
extern "C" void kernel_launch(void* const* d_in, const int* in_sizes, int n_in,
                              void* d_out, int out_size)
{
    const int*   row  = (const int*)  d_in[0];
    const int*   col  = (const int*)  d_in[1];
    const float* vals = (const float*)d_in[2];
    const float* X    = (const float*)d_in[3];
    const float* W    = (const float*)d_in[4];
    const float* bias = (const float*)d_in[5];
    float*       out  = (float*)d_out;

    int E = in_sizes[0];
    int N = in_sizes[3] / D;   // 100000

    int nb_scan = (N + SCAN_B - 1) / SCAN_B;          // 98
    int nb_edge = (E + 511) / 512;

    zero_cnt_kernel<<<nb_scan, SCAN_B>>>(N);
    hist_kernel<<<nb_edge, 512>>>(row, E);
    scan_a_kernel<<<nb_scan, SCAN_B>>>(N);
    scan_b_kernel<<<1, 128>>>(nb_scan, N);
    scan_c_kernel<<<nb_scan, SCAN_B>>>(N);
    bin_kernel<<<nb_edge, 512>>>(row, col, vals, E);

    int threads_gather = N * DV;                       // 16 lanes per node
    gather_kernel<<<(threads_gather + 255) / 256, 256>>>((const float4*)X, N);

    gemm_bias_kernel<<<(N + 63) / 64, 256>>>(W, (const float4*)bias,
                                             (float4*)out, N);
}

// round 8
// speedup vs baseline: 1.1615x; 1.0301x over previous
#include <cuda_runtime.h>

#define D       64
#define DV      16          // D/4 float4 per row
#define MAX_N   100000
#define MAX_E   1700000
#define SCAN_B  1024

// ---------------------------------------------------------------------------
// Device-global scratch (no allocation allowed)
// g_cnt is zero at module load and restored to zero by scan_a every execution.
// ---------------------------------------------------------------------------
__device__ int    g_cnt[MAX_N];        // histogram of destination rows (self-restoring)
__device__ int    g_off[MAX_N + 1];    // exclusive CSR offsets
__device__ int    g_pos[MAX_N];        // working cursor for binning
__device__ int    g_bsum[256];         // per-block scan totals
__device__ int2   g_edge[MAX_E];       // binned (col, val-bits) pairs
__device__ float4 g_Y[MAX_N * DV];     // Y = X @ W^T

// ---------------------------------------------------------------------------
// Branch A1) histogram of row[]
// ---------------------------------------------------------------------------
__global__ __launch_bounds__(512) void hist_kernel(const int* __restrict__ row, int E) {
    int e = blockIdx.x * 512 + threadIdx.x;
    if (e < E) atomicAdd(&g_cnt[__ldg(row + e)], 1);
}

// ---------------------------------------------------------------------------
// Branch A2) per-block exclusive scan of g_cnt -> g_off ; block totals ->
//            g_bsum ; zero g_cnt for the next execution.
// ---------------------------------------------------------------------------
__global__ __launch_bounds__(SCAN_B) void scan_a_kernel(int N) {
    int i = blockIdx.x * SCAN_B + threadIdx.x;
    int v = 0;
    if (i < N) { v = g_cnt[i]; g_cnt[i] = 0; }   // read + restore invariant

    int lane = threadIdx.x & 31;
    int wid  = threadIdx.x >> 5;

    int s = v;
#pragma unroll
    for (int d = 1; d < 32; d <<= 1) {
        int t = __shfl_up_sync(0xFFFFFFFFu, s, d);
        if (lane >= d) s += t;
    }
    __shared__ int wsum[32];
    if (lane == 31) wsum[wid] = s;
    __syncthreads();
    if (wid == 0) {
        int ws = wsum[lane];
#pragma unroll
        for (int d = 1; d < 32; d <<= 1) {
            int t = __shfl_up_sync(0xFFFFFFFFu, ws, d);
            if (lane >= d) ws += t;
        }
        wsum[lane] = ws;
    }
    __syncthreads();
    int incl = s + (wid == 0 ? 0 : wsum[wid - 1]);
    if (i < N) g_off[i] = incl - v;                          // block-local exclusive
    if (threadIdx.x == SCAN_B - 1) g_bsum[blockIdx.x] = incl; // block total
}

// ---------------------------------------------------------------------------
// Branch A3) fused block-prefix + finalize: each block reduces the totals of
//            all preceding blocks (<=128 values), adds to its elements, and
//            initializes the bin cursors. g_off[N] = E from host.
// ---------------------------------------------------------------------------
__global__ __launch_bounds__(SCAN_B) void scan_bc_kernel(int NB, int N, int E) {
    __shared__ int s_part[4];
    __shared__ int s_pref;

    int tid = threadIdx.x;
    if (tid < 128) {
        int vp = (tid < blockIdx.x) ? g_bsum[tid] : 0;   // blockIdx.x <= NB <= 128
#pragma unroll
        for (int d = 16; d >= 1; d >>= 1)
            vp += __shfl_down_sync(0xFFFFFFFFu, vp, d);
        if ((tid & 31) == 0) s_part[tid >> 5] = vp;
    }
    __syncthreads();
    if (tid == 0) {
        s_pref = s_part[0] + s_part[1] + s_part[2] + s_part[3];
        if (blockIdx.x == 0) g_off[N] = E;
    }
    __syncthreads();

    int pref = s_pref;
    int i = blockIdx.x * SCAN_B + tid;
    if (i < N) {
        int o = g_off[i] + pref;
        g_off[i] = o;
        g_pos[i] = o;
    }
}

// ---------------------------------------------------------------------------
// Branch A4) bin edges into CSR order: g_edge[pos] = (col, val)
// ---------------------------------------------------------------------------
__global__ __launch_bounds__(512) void bin_kernel(
    const int* __restrict__ row, const int* __restrict__ col,
    const float* __restrict__ vals, int E)
{
    int e = blockIdx.x * 512 + threadIdx.x;
    if (e < E) {
        int r = __ldg(row + e);
        int p = atomicAdd(&g_pos[r], 1);
        g_edge[p] = make_int2(__ldg(col + e), __float_as_int(__ldg(vals + e)));
    }
}

// ---------------------------------------------------------------------------
// Branch B) Y = X @ W^T  (register-tiled GEMM, 64x64 tile, 4x4 micro-tile)
// Runs CONCURRENTLY with branch A on a forked stream.
// ---------------------------------------------------------------------------
#define TPAD 68   // row stride in floats (272B, 16B-aligned)

__global__ __launch_bounds__(256) void xform_kernel(
    const float* __restrict__ X,      // [N, 64]
    const float* __restrict__ W,      // [64, 64]
    int N)
{
    __shared__ float Xs[D * TPAD];   // Xs[k][m]
    __shared__ float Ws[D * TPAD];   // Ws[k][o]

    const int tid = threadIdx.x;
    const int node0 = blockIdx.x * 64;

    {
        int r  = tid >> 4;
        int cv = tid & 15;
#pragma unroll
        for (int p = 0; p < 4; p++) {
            int rowi = r + p * 16;
            float4 w = *(const float4*)(W + rowi * D + cv * 4);
            Ws[(cv * 4 + 0) * TPAD + rowi] = w.x;
            Ws[(cv * 4 + 1) * TPAD + rowi] = w.y;
            Ws[(cv * 4 + 2) * TPAD + rowi] = w.z;
            Ws[(cv * 4 + 3) * TPAD + rowi] = w.w;
            int n = node0 + rowi;
            float4 x = (n < N) ? *(const float4*)(X + (size_t)n * D + cv * 4)
                               : make_float4(0.f, 0.f, 0.f, 0.f);
            Xs[(cv * 4 + 0) * TPAD + rowi] = x.x;
            Xs[(cv * 4 + 1) * TPAD + rowi] = x.y;
            Xs[(cv * 4 + 2) * TPAD + rowi] = x.z;
            Xs[(cv * 4 + 3) * TPAD + rowi] = x.w;
        }
    }
    __syncthreads();

    const int tx = tid & 15;
    const int ty = tid >> 4;
    const int m4 = ty * 4;
    const int n4 = tx * 4;

    float acc[4][4];
#pragma unroll
    for (int i = 0; i < 4; i++)
#pragma unroll
        for (int j = 0; j < 4; j++) acc[i][j] = 0.f;

#pragma unroll 8
    for (int k = 0; k < D; k++) {
        float4 xf = *(const float4*)(Xs + k * TPAD + m4);
        float4 wf = *(const float4*)(Ws + k * TPAD + n4);
        const float xv[4] = {xf.x, xf.y, xf.z, xf.w};
        const float wv[4] = {wf.x, wf.y, wf.z, wf.w};
#pragma unroll
        for (int i = 0; i < 4; i++)
#pragma unroll
            for (int j = 0; j < 4; j++)
                acc[i][j] += xv[i] * wv[j];
    }

#pragma unroll
    for (int i = 0; i < 4; i++) {
        int n = node0 + m4 + i;
        if (n < N)
            g_Y[(size_t)n * DV + tx] =
                make_float4(acc[i][0], acc[i][1], acc[i][2], acc[i][3]);
    }
}

// ---------------------------------------------------------------------------
// Join) gather: out[n] = bias + sum over in-edges of val * Y[col]
//       16 lanes per node, lane q owns float4 chunk q. Unroll 8/4 for MLP.
// ---------------------------------------------------------------------------
__global__ __launch_bounds__(256) void gather_bias_kernel(
    const float4* __restrict__ bias,   // [16]
    float4*       __restrict__ out,    // [N*16]
    int N)
{
    int t = blockIdx.x * 256 + threadIdx.x;
    int n = t >> 4;
    int q = t & 15;
    if (n >= N) return;

    int s = __ldg(&g_off[n]);
    int e = __ldg(&g_off[n + 1]);

    float4 acc = __ldg(bias + q);
    int j = s;

    for (; j + 8 <= e; j += 8) {
        int2 p[8];
#pragma unroll
        for (int u = 0; u < 8; u++) p[u] = g_edge[j + u];
        float4 x[8];
#pragma unroll
        for (int u = 0; u < 8; u++)
            x[u] = __ldg(&g_Y[(size_t)p[u].x * DV + q]);
#pragma unroll
        for (int u = 0; u < 8; u++) {
            float v = __int_as_float(p[u].y);
            acc.x += v * x[u].x; acc.y += v * x[u].y;
            acc.z += v * x[u].z; acc.w += v * x[u].w;
        }
    }
    for (; j + 4 <= e; j += 4) {
        int2 p[4];
#pragma unroll
        for (int u = 0; u < 4; u++) p[u] = g_edge[j + u];
        float4 x[4];
#pragma unroll
        for (int u = 0; u < 4; u++)
            x[u] = __ldg(&g_Y[(size_t)p[u].x * DV + q]);
#pragma unroll
        for (int u = 0; u < 4; u++) {
            float v = __int_as_float(p[u].y);
            acc.x += v * x[u].x; acc.y += v * x[u].y;
            acc.z += v * x[u].z; acc.w += v * x[u].w;
        }
    }
    for (; j < e; j++) {
        int2 p = g_edge[j];
        float4 x = __ldg(&g_Y[(size_t)p.x * DV + q]);
        float v = __int_as_float(p.y);
        acc.x += v * x.x; acc.y += v * x.y; acc.z += v * x.z; acc.w += v * x.w;
    }
    out[(size_t)n * DV + q] = acc;
}

// ---------------------------------------------------------------------------
// Launch: inputs in metadata order: row, col, vals, X, weight, bias
// Fork/join via event pattern so the GEMM branch captures as a parallel
// graph branch. Stream/events are created fresh per call and intentionally
// never destroyed (kernel_launch is invoked only a handful of times;
// destroying capture-participating resources mid-capture is illegal).
// ---------------------------------------------------------------------------
extern "C" void kernel_launch(void* const* d_in, const int* in_sizes, int n_in,
                              void* d_out, int out_size)
{
    const int*   row  = (const int*)  d_in[0];
    const int*   col  = (const int*)  d_in[1];
    const float* vals = (const float*)d_in[2];
    const float* X    = (const float*)d_in[3];
    const float* W    = (const float*)d_in[4];
    const float* bias = (const float*)d_in[5];
    float*       out  = (float*)d_out;

    int E = in_sizes[0];
    int N = in_sizes[3] / D;   // 100000

    int nb_scan = (N + SCAN_B - 1) / SCAN_B;          // 98
    int nb_edge = (E + 511) / 512;

    cudaStream_t s2;
    cudaEvent_t evFork, evJoin;
    cudaStreamCreateWithFlags(&s2, cudaStreamNonBlocking);
    cudaEventCreateWithFlags(&evFork, cudaEventDisableTiming);
    cudaEventCreateWithFlags(&evJoin, cudaEventDisableTiming);

    // Fork: branch B (GEMM) on s2
    cudaEventRecord(evFork, 0);
    cudaStreamWaitEvent(s2, evFork, 0);
    xform_kernel<<<(N + 63) / 64, 256, 0, s2>>>(X, W, N);

    // Branch A (CSR build) on the capturing (default) stream
    hist_kernel<<<nb_edge, 512>>>(row, E);
    scan_a_kernel<<<nb_scan, SCAN_B>>>(N);
    scan_bc_kernel<<<nb_scan, SCAN_B>>>(nb_scan, N, E);
    bin_kernel<<<nb_edge, 512>>>(row, col, vals, E);

    // Join
    cudaEventRecord(evJoin, s2);
    cudaStreamWaitEvent(0, evJoin, 0);

    int threads_gather = N * DV;                       // 16 lanes per node
    gather_bias_kernel<<<(threads_gather + 255) / 256, 256>>>(
        (const float4*)bias, (float4*)out, N);
}